// round 7
// baseline (speedup 1.0000x reference)
#include <cuda_runtime.h>
#include <cuda_fp16.h>
#include <math.h>
#include <stdint.h>

#define BB 64
#define LL 256
#define HH 1024
#define EE 1024
#define VV 50257
#define H3 3072

// ================= scratch (__device__ globals) =============================
__device__ __align__(16) __half g_xhi[BB * 1024];
__device__ __align__(16) __half g_xlo[BB * 1024];
__device__ __align__(16) __half g_hhi[BB * 1024];
__device__ __align__(16) __half g_hlo[BB * 1024];
__device__ __align__(16) __half g_chi[BB * 1024];
__device__ __align__(16) __half g_cat_hi[BB * 2 * HH];
__device__ __align__(16) __half g_cat_lo[BB * 2 * HH];
__device__ float g_gi[2 * BB * H3];            // k-split partials
__device__ float g_gh[2 * BB * H3];
__device__ float g_hb[BB];
__device__ float g_q[BB * HH];
__device__ float g_qpart[8 * BB * HH];
__device__ float g_scores[BB * LL];
__device__ float g_cpart[8 * BB * HH];

// ================= helpers ===================================================
__device__ __forceinline__ uint32_t smem_u32(const void* p) {
    uint32_t a;
    asm("{ .reg .u64 t; cvta.to.shared.u64 t, %1; cvt.u32.u64 %0, t; }"
        : "=r"(a) : "l"(p));
    return a;
}

__device__ __forceinline__ void ldsm_x4(uint32_t addr, uint32_t& d0, uint32_t& d1,
                                        uint32_t& d2, uint32_t& d3) {
    asm volatile("ldmatrix.sync.aligned.m8n8.x4.shared.b16 {%0,%1,%2,%3}, [%4];"
                 : "=r"(d0), "=r"(d1), "=r"(d2), "=r"(d3) : "r"(addr));
}

__device__ __forceinline__ void mma_f16(float* c, uint32_t a0, uint32_t a1,
                                        uint32_t a2, uint32_t a3,
                                        uint32_t b0, uint32_t b1) {
    asm volatile(
        "mma.sync.aligned.m16n8k16.row.col.f32.f16.f16.f32 "
        "{%0,%1,%2,%3}, {%4,%5,%6,%7}, {%8,%9}, {%0,%1,%2,%3};"
        : "+f"(c[0]), "+f"(c[1]), "+f"(c[2]), "+f"(c[3])
        : "r"(a0), "r"(a1), "r"(a2), "r"(a3), "r"(b0), "r"(b1));
}

__device__ __forceinline__ uint32_t pack_h(float a, float b) {
    __half2 t = __floats2half2_rn(a, b);
    return *reinterpret_cast<uint32_t*>(&t);
}

// ================= double-buffered fused-convert HMMA GEMM (fp16) ===========
// C[64, n] = sum_k fp32(A[64,k]) * W[n,k] (+bias), fp16 hi/lo compensated.
// NP=3: Ahi*Whi + Ahi*Wlo + Alo*Whi (err ~2^-22) — pre-softmax math.
// NP=2: Ahi*Whi + Ahi*Wlo           (err ~2^-12) — logits GEMM.
// WIDE=0: CTA 64x128, 8 warps 4x2 of 16x64.
// WIDE=1: CTA 64x256, 8 warps 2x4 of 32x64 (half smem-read redundancy).
// W fp32 read exactly once, converted in-register.
// gridDim.z = split-K; partial z -> C + z*pstride (bias only if pstride==0).
#define STR 40

template <int NP, int WIDE>
__global__ __launch_bounds__(256, 2)
void hmma_gemm(const __half* __restrict__ Ahi0, const __half* __restrict__ Alo0,
               const float* __restrict__ W0, float* __restrict__ C0,
               const __half* __restrict__ Ahi1, const __half* __restrict__ Alo1,
               const float* __restrict__ W1, float* __restrict__ C1,
               const float* __restrict__ bias, int Ntot, int K, int ldc,
               long pstride, int lda, int ldw, int wtrans) {
    extern __shared__ __half sm[];

    constexpr int NTILE = WIDE ? 256 : 128;
    constexpr int NROWSW = WIDE ? 256 : 128;
    constexpr int MF = WIDE ? 2 : 1;          // m16 frags per warp
    constexpr int WK = WIDE ? 32 : 16;        // W floats staged per thread
    constexpr int OFF_ALO_ = 64 * STR;
    constexpr int OFF_WHI_ = 128 * STR;
    constexpr int OFF_WLO_ = OFF_WHI_ + NROWSW * STR;
    constexpr int STG_ELEMS = OFF_WLO_ + NROWSW * STR;
    constexpr int STG_BYTES = STG_ELEMS * 2;

    const __half* Ahi = blockIdx.y ? Ahi1 : Ahi0;
    const __half* Alo = blockIdx.y ? Alo1 : Alo0;
    const float* W = blockIdx.y ? W1 : W0;
    float* C = (blockIdx.y ? C1 : C0) + (size_t)blockIdx.z * pstride;

    const int tid = threadIdx.x, wid = tid >> 5, lane = tid & 31;
    const int warp_m_base = WIDE ? (wid & 1) * 32 : (wid & 3) * 16;
    const int warp_n_base = WIDE ? (wid >> 1) * 64 : (wid >> 2) * 64;
    const int n0 = blockIdx.x * NTILE;

    const int kper = K / gridDim.z;
    const int koff = blockIdx.z * kper;
    const int nchunks = kper >> 5;

    // --- staging ids ---
    const int wrow_idx = WIDE ? tid : (tid >> 1);
    const int wkoff = WIDE ? 0 : (tid & 1) * 16;   // in k-elements (halves)
    const bool wv = (n0 + wrow_idx) < Ntot;
    const float* wrow = W + (size_t)(n0 + wrow_idx) * K + koff + wkoff;
    const float* wtb  = W + (size_t)(koff + wkoff) * ldw + (n0 + wrow_idx);
    const int ar = tid >> 1, ahf = tid & 1;
    const __half* arow_hi = Ahi + (size_t)(ar & 63) * lda + koff + ahf * 16;
    const __half* arow_lo = Alo + (size_t)(ar & 63) * lda + koff + ahf * 16;
    const bool do_a = (tid < 128);

    // --- ldmatrix base addresses ---
    const int am = lane >> 3, aln = lane & 7;
    uint32_t aHiB[2], aLoB[2];
#pragma unroll
    for (int mi = 0; mi < MF; mi++) {
        int arow2 = warp_m_base + mi * 16 + aln + (am & 1) * 8;
        aHiB[mi] = smem_u32(&sm[arow2 * STR + (am >> 1) * 8]);
        aLoB[mi] = smem_u32(&sm[OFF_ALO_ + arow2 * STR + (am >> 1) * 8]);
    }
    const int brow_base = warp_n_base + aln + (am >> 1) * 8;
    const int bkoff = (am & 1) * 8;
    const uint32_t bHiB = smem_u32(&sm[OFF_WHI_ + brow_base * STR + bkoff]);
    const uint32_t bLoB = smem_u32(&sm[OFF_WLO_ + brow_base * STR + bkoff]);

    float acc[MF * 8][4];
#pragma unroll
    for (int i = 0; i < MF * 8; i++)
#pragma unroll
        for (int j = 0; j < 4; j++) acc[i][j] = 0.f;

    float wreg[WK];
    uint4 ahreg[2], alreg[2];

    auto load_chunk = [&](int ck) {
        if (wv) {
            if (!wtrans) {
                const float4* p = (const float4*)(wrow + (size_t)ck * 32);
#pragma unroll
                for (int i = 0; i < WK / 4; i++) {
                    float4 f = p[i];
                    wreg[i * 4 + 0] = f.x; wreg[i * 4 + 1] = f.y;
                    wreg[i * 4 + 2] = f.z; wreg[i * 4 + 3] = f.w;
                }
            } else {
                const float* p = wtb + (size_t)ck * 32 * ldw;
#pragma unroll
                for (int i = 0; i < WK; i++) wreg[i] = p[(size_t)i * ldw];
            }
        }
        if (do_a) {
            const uint4* ph = (const uint4*)(arow_hi + (size_t)ck * 32);
            ahreg[0] = ph[0]; ahreg[1] = ph[1];
            if (NP == 3) {
                const uint4* pl = (const uint4*)(arow_lo + (size_t)ck * 32);
                alreg[0] = pl[0]; alreg[1] = pl[1];
            }
        }
    };

    auto store_stage = [&](int st) {
        const int so = st * STG_ELEMS;
        int wb = so + OFF_WHI_ + wrow_idx * STR + wkoff;
        int wb2 = so + OFF_WLO_ + wrow_idx * STR + wkoff;
#pragma unroll
        for (int qq = 0; qq < WK / 8; qq++) {
            uint4 hv, lv;
            float f0 = wreg[qq * 8 + 0], f1 = wreg[qq * 8 + 1];
            float f2 = wreg[qq * 8 + 2], f3 = wreg[qq * 8 + 3];
            float f4 = wreg[qq * 8 + 4], f5 = wreg[qq * 8 + 5];
            float f6 = wreg[qq * 8 + 6], f7 = wreg[qq * 8 + 7];
            float h0 = __half2float(__float2half_rn(f0));
            float h1 = __half2float(__float2half_rn(f1));
            float h2 = __half2float(__float2half_rn(f2));
            float h3 = __half2float(__float2half_rn(f3));
            float h4 = __half2float(__float2half_rn(f4));
            float h5 = __half2float(__float2half_rn(f5));
            float h6 = __half2float(__float2half_rn(f6));
            float h7 = __half2float(__float2half_rn(f7));
            hv.x = pack_h(f0, f1); hv.y = pack_h(f2, f3);
            hv.z = pack_h(f4, f5); hv.w = pack_h(f6, f7);
            lv.x = pack_h(f0 - h0, f1 - h1); lv.y = pack_h(f2 - h2, f3 - h3);
            lv.z = pack_h(f4 - h4, f5 - h5); lv.w = pack_h(f6 - h6, f7 - h7);
            *(uint4*)&sm[wb + qq * 8] = hv;
            *(uint4*)&sm[wb2 + qq * 8] = lv;
        }
        if (do_a) {
            int ab = so + ar * STR + ahf * 16;
            *(uint4*)&sm[ab + 0] = ahreg[0];
            *(uint4*)&sm[ab + 8] = ahreg[1];
            if (NP == 3) {
                int ab2 = so + OFF_ALO_ + ar * STR + ahf * 16;
                *(uint4*)&sm[ab2 + 0] = alreg[0];
                *(uint4*)&sm[ab2 + 8] = alreg[1];
            }
        }
    };

    if (!wv) {
#pragma unroll
        for (int i = 0; i < WK; i++) wreg[i] = 0.f;
    }

    load_chunk(0);
    store_stage(0);
    __syncthreads();

    for (int ck = 0; ck < nchunks; ck++) {
        const bool more = (ck + 1 < nchunks);
        if (more) load_chunk(ck + 1);

        const uint32_t so = (uint32_t)(ck & 1) * STG_BYTES;
#pragma unroll
        for (int ks = 0; ks < 2; ks++) {
            uint32_t ah[2][4], al[2][4];
#pragma unroll
            for (int mi = 0; mi < MF; mi++) {
                ldsm_x4(aHiB[mi] + so + ks * 32,
                        ah[mi][0], ah[mi][1], ah[mi][2], ah[mi][3]);
                if (NP == 3)
                    ldsm_x4(aLoB[mi] + so + ks * 32,
                            al[mi][0], al[mi][1], al[mi][2], al[mi][3]);
            }
#pragma unroll
            for (int nf = 0; nf < 4; nf++) {
                const uint32_t off = so + nf * (16 * STR * 2) + ks * 32;
                uint32_t bh0, bh1, bh2, bh3, bl0, bl1, bl2, bl3;
                ldsm_x4(bHiB + off, bh0, bh1, bh2, bh3);
                ldsm_x4(bLoB + off, bl0, bl1, bl2, bl3);
#pragma unroll
                for (int mi = 0; mi < MF; mi++) {
                    const int ix = mi * 8 + nf * 2;
                    mma_f16(acc[ix],     ah[mi][0], ah[mi][1], ah[mi][2], ah[mi][3], bh0, bh1);
                    mma_f16(acc[ix + 1], ah[mi][0], ah[mi][1], ah[mi][2], ah[mi][3], bh2, bh3);
                    mma_f16(acc[ix],     ah[mi][0], ah[mi][1], ah[mi][2], ah[mi][3], bl0, bl1);
                    mma_f16(acc[ix + 1], ah[mi][0], ah[mi][1], ah[mi][2], ah[mi][3], bl2, bl3);
                    if (NP == 3) {
                        mma_f16(acc[ix],     al[mi][0], al[mi][1], al[mi][2], al[mi][3], bh0, bh1);
                        mma_f16(acc[ix + 1], al[mi][0], al[mi][1], al[mi][2], al[mi][3], bh2, bh3);
                    }
                }
            }
        }

        if (more) store_stage((ck + 1) & 1);
        __syncthreads();
    }

    const int qrow = lane >> 2, qcol = (lane & 3) * 2;
    const bool use_bias = (bias != nullptr) && (pstride == 0);
#pragma unroll
    for (int mi = 0; mi < MF; mi++) {
        const int m0 = warp_m_base + mi * 16 + qrow;
#pragma unroll
        for (int nf = 0; nf < 4; nf++)
#pragma unroll
            for (int p = 0; p < 2; p++) {
                int n = n0 + warp_n_base + nf * 16 + p * 8 + qcol;
                const float* a = acc[mi * 8 + nf * 2 + p];
                float b0v = 0.f, b1v = 0.f;
                if (use_bias) {
                    if (n < Ntot) b0v = bias[n];
                    if (n + 1 < Ntot) b1v = bias[n + 1];
                }
                if (n < Ntot) {
                    C[(size_t)m0 * ldc + n] = a[0] + b0v;
                    C[(size_t)(m0 + 8) * ldc + n] = a[2] + b0v;
                }
                if (n + 1 < Ntot) {
                    C[(size_t)m0 * ldc + n + 1] = a[1] + b1v;
                    C[(size_t)(m0 + 8) * ldc + n + 1] = a[3] + b1v;
                }
            }
    }
}

#define HMMA_SMEM_N ((128 * STR + 2 * 128 * STR) * 2 * 2)
#define HMMA_SMEM_W ((128 * STR + 2 * 256 * STR) * 2 * 2)

// ================= fused hi/lo split prep (emb gather + h0) ==================
__global__ void split_all(const int* __restrict__ seq, const float* __restrict__ emb,
                          const float* __restrict__ h0,
                          __half* __restrict__ xhi, __half* __restrict__ xlo,
                          __half* __restrict__ hhi, __half* __restrict__ hlo) {
    int r = blockIdx.x, t = threadIdx.x;
    const float* src;
    __half *hi, *lo;
    int row;
    if (r < BB) {
        src = emb + (size_t)seq[r] * EE; hi = xhi; lo = xlo; row = r;
    } else {
        row = r - BB;
        src = h0 + (size_t)row * HH; hi = hhi; lo = hlo;
    }
    for (int j = t; j < 1024; j += 256) {
        float f = src[j];
        __half h = __float2half_rn(f);
        hi[row * 1024 + j] = h;
        lo[row * 1024 + j] = __float2half_rn(f - __half2float(h));
    }
}

// ================= split-K reducers ==========================================
__global__ void reduce_ba(const float* __restrict__ P, int nsplit, int ntot,
                          int N, const float* __restrict__ bias,
                          float* __restrict__ C, int act) {
    int idx = blockIdx.x * blockDim.x + threadIdx.x;
    if (idx >= ntot) return;
    float s = 0.f;
    for (int p = 0; p < nsplit; p++) s += P[(size_t)p * ntot + idx];
    if (bias) s += bias[idx % N];
    if (act) s = tanhf(s);
    C[idx] = s;
}

__global__ void reduce_tanh_split(const float* __restrict__ P,
                                  const float* __restrict__ bias,
                                  __half* __restrict__ hi) {
    int idx = blockIdx.x * blockDim.x + threadIdx.x;  // 65536
    float s = 0.f;
#pragma unroll
    for (int p = 0; p < 8; p++) s += P[(size_t)p * (BB * HH) + idx];
    s = tanhf(s + bias[idx & 1023]);
    hi[idx] = __float2half_rn(s);
}

// ================= fused GRU combine + hb reduction ==========================
__global__ void gru_combine_hb(const float* __restrict__ gi,
                               const float* __restrict__ gh,
                               const float* __restrict__ b_ih,
                               const float* __restrict__ b_hh,
                               const float* __restrict__ hprev,
                               const float* __restrict__ attn_b,
                               __half* __restrict__ cat_hi,
                               __half* __restrict__ cat_lo,
                               float* __restrict__ out_hidden,
                               float* __restrict__ hb) {
    int b = blockIdx.x, t = threadIdx.x;
    const int P = BB * H3;
    float hb_acc = 0.f;
#pragma unroll
    for (int ii = 0; ii < 4; ii++) {
        int j = t + ii * 256;
        size_t base = (size_t)b * H3 + j;
        float ir = gi[base] + gi[P + base] + b_ih[j];
        float iz = gi[base + HH] + gi[P + base + HH] + b_ih[HH + j];
        float in_ = gi[base + 2 * HH] + gi[P + base + 2 * HH] + b_ih[2 * HH + j];
        float hr = gh[base] + gh[P + base] + b_hh[j];
        float hz = gh[base + HH] + gh[P + base + HH] + b_hh[HH + j];
        float hn = gh[base + 2 * HH] + gh[P + base + 2 * HH] + b_hh[2 * HH + j];
        float r = 1.f / (1.f + expf(-(ir + hr)));
        float z = 1.f / (1.f + expf(-(iz + hz)));
        float n = tanhf(in_ + r * hn);
        float hp = hprev[(size_t)b * HH + j];
        float hnew = (1.f - z) * n + z * hp;
        out_hidden[(size_t)b * HH + j] = hnew;
        __half h = __float2half_rn(hnew);
        cat_hi[(size_t)b * 2048 + j] = h;
        cat_lo[(size_t)b * 2048 + j] = __float2half_rn(hnew - __half2float(h));
        hb_acc += hnew * attn_b[j];
    }
    __shared__ float smr[256];
    smr[t] = hb_acc;
    __syncthreads();
    for (int st = 128; st > 0; st >>= 1) {
        if (t < st) smr[t] += smr[t + st];
        __syncthreads();
    }
    if (t == 0) hb[b] = smr[0];
}

// ================= attention kernels =========================================
__global__ void scores_kernel(const float* __restrict__ q,
                              const float* __restrict__ enc,
                              const float* __restrict__ hb,
                              float* __restrict__ scores) {
    int pair = blockIdx.x * 8 + (threadIdx.x >> 5);
    int lane = threadIdx.x & 31;
    int b = pair >> 8, l = pair & 255;
    const float* e = enc + ((size_t)l * BB + b) * HH;
    const float* qr = q + (size_t)b * HH;
    float s = 0.f;
#pragma unroll
    for (int i = 0; i < 8; i++) {
        int h = lane * 4 + i * 128;
        float4 ev = *(const float4*)(e + h);
        float4 qv = *(const float4*)(qr + h);
        s += ev.x * qv.x + ev.y * qv.y + ev.z * qv.z + ev.w * qv.w;
    }
#pragma unroll
    for (int o = 16; o > 0; o >>= 1) s += __shfl_xor_sync(0xffffffffu, s, o);
    if (lane == 0) scores[(size_t)b * LL + l] = s + hb[b];
}

// fused softmax (redundant per y-block) + context slice
__global__ void softmax_context(const float* __restrict__ scores,
                                const float* __restrict__ enc,
                                float* __restrict__ out_attn,
                                __half* __restrict__ cat_hi,
                                __half* __restrict__ cat_lo) {
    int b = blockIdx.x, t = threadIdx.x;
    __shared__ float w[256];
    __shared__ float red[128];
    float v0 = scores[(size_t)b * LL + t];
    float v1 = scores[(size_t)b * LL + t + 128];
    red[t] = fmaxf(v0, v1);
    __syncthreads();
    for (int s = 64; s > 0; s >>= 1) {
        if (t < s) red[t] = fmaxf(red[t], red[t + s]);
        __syncthreads();
    }
    float mx = red[0];
    __syncthreads();
    float e0 = expf(v0 - mx), e1 = expf(v1 - mx);
    red[t] = e0 + e1;
    __syncthreads();
    for (int s = 64; s > 0; s >>= 1) {
        if (t < s) red[t] += red[t + s];
        __syncthreads();
    }
    float inv = 1.f / red[0];
    float w0 = e0 * inv, w1 = e1 * inv;
    w[t] = w0; w[t + 128] = w1;
    if (blockIdx.y == 0) {
        out_attn[(size_t)b * LL + t] = w0;
        out_attn[(size_t)b * LL + t + 128] = w1;
    }
    __syncthreads();

    int hc = blockIdx.y * 128 + t;
    float acc = 0.f;
    const float* e = enc + (size_t)b * HH + hc;
    for (int l0 = 0; l0 < LL; l0 += 16) {
        float v[16];
#pragma unroll
        for (int u = 0; u < 16; u++)
            v[u] = e[(size_t)(l0 + u) * BB * HH];
#pragma unroll
        for (int u = 0; u < 16; u++)
            acc += w[l0 + u] * v[u];
    }
    size_t o = (size_t)b * 2048 + 1024 + hc;
    __half h = __float2half_rn(acc);
    cat_hi[o] = h;
    cat_lo[o] = __float2half_rn(acc - __half2float(h));
}

// ================= launch =====================================================
extern "C" void kernel_launch(void* const* d_in, const int* in_sizes, int n_in,
                              void* d_out, int out_size) {
    const int*   seq  = (const int*)d_in[0];
    const float* h0   = (const float*)d_in[1];
    const float* enc  = (const float*)d_in[2];
    const float* emb  = (const float*)d_in[3];
    const float* w_ih = (const float*)d_in[4];
    const float* w_hh = (const float*)d_in[5];
    const float* b_ih = (const float*)d_in[6];
    const float* b_hh = (const float*)d_in[7];
    const float* attw = (const float*)d_in[8];
    const float* attb = (const float*)d_in[9];
    const float* cw   = (const float*)d_in[10];
    const float* cb   = (const float*)d_in[11];
    const float* ow   = (const float*)d_in[12];
    const float* ob   = (const float*)d_in[13];

    float* out        = (float*)d_out;                  // [B, V]
    float* out_hidden = out + (size_t)BB * VV;          // [B, H]
    float* out_attn   = out_hidden + (size_t)BB * HH;   // [B, L]

    cudaFuncSetAttribute(hmma_gemm<3, 0>, cudaFuncAttributeMaxDynamicSharedMemorySize,
                         HMMA_SMEM_N);
    cudaFuncSetAttribute(hmma_gemm<2, 1>, cudaFuncAttributeMaxDynamicSharedMemorySize,
                         HMMA_SMEM_W);

    __half *xhi, *xlo, *hhi, *hlo, *chi, *cathi, *catlo;
    float *gi, *gh, *hb, *q, *qp, *sc, *cp;
    cudaGetSymbolAddress((void**)&xhi, g_xhi);
    cudaGetSymbolAddress((void**)&xlo, g_xlo);
    cudaGetSymbolAddress((void**)&hhi, g_hhi);
    cudaGetSymbolAddress((void**)&hlo, g_hlo);
    cudaGetSymbolAddress((void**)&chi, g_chi);
    cudaGetSymbolAddress((void**)&cathi, g_cat_hi);
    cudaGetSymbolAddress((void**)&catlo, g_cat_lo);
    cudaGetSymbolAddress((void**)&gi, g_gi);
    cudaGetSymbolAddress((void**)&gh, g_gh);
    cudaGetSymbolAddress((void**)&hb, g_hb);
    cudaGetSymbolAddress((void**)&q, g_q);
    cudaGetSymbolAddress((void**)&qp, g_qpart);
    cudaGetSymbolAddress((void**)&sc, g_scores);
    cudaGetSymbolAddress((void**)&cp, g_cpart);

    // 1) fp16 hi/lo splits: emb gather + h0
    split_all<<<128, 256>>>(seq, emb, h0, xhi, xlo, hhi, hlo);

    // 2) GRU gate GEMMs (3-pass narrow; two problems via grid.y, split-K=2)
    hmma_gemm<3, 0><<<dim3(24, 2, 2), 256, HMMA_SMEM_N>>>(
        xhi, xlo, w_ih, gi, hhi, hlo, w_hh, gh,
        nullptr, H3, EE, H3, (long)BB * H3, EE, 0, 0);

    // 3) gates -> h_new (hidden output, cat hi/lo first half, hb)
    gru_combine_hb<<<BB, 256>>>(gi, gh, b_ih, b_hh, h0, attb,
                                cathi, catlo, out_hidden, hb);

    // 4) q = h_new @ attn_w (3-pass narrow, transposed W, split-K=8) + reduce
    hmma_gemm<3, 0><<<dim3(8, 1, 8), 256, HMMA_SMEM_N>>>(
        cathi, catlo, attw, qp, cathi, catlo, attw, qp,
        nullptr, HH, HH, HH, (long)BB * HH, 2048, HH, 1);
    reduce_ba<<<(BB * HH) / 256, 256>>>(qp, 8, BB * HH, HH, nullptr, q, 0);

    // 5) scores = q . enc + hb ; fused softmax+context
    scores_kernel<<<2048, 256>>>(q, enc, hb, sc);
    softmax_context<<<dim3(BB, 8), 128>>>(sc, enc, out_attn, cathi, catlo);

    // 6) concat GEMM (3-pass narrow, K=2048, split-K=8) -> tanh+fp16 reduce
    hmma_gemm<3, 0><<<dim3(8, 1, 8), 256, HMMA_SMEM_N>>>(
        cathi, catlo, cw, cp, cathi, catlo, cw, cp,
        nullptr, HH, 2048, HH, (long)BB * HH, 2048, 0, 0);
    reduce_tanh_split<<<(BB * HH) / 256, 256>>>(cp, cb, chi);

    // 7) big V-GEMM: 2-pass fp16, WIDE 64x256 tiles (197 CTAs = one wave)
    hmma_gemm<2, 1><<<dim3((VV + 255) / 256, 1, 1), 256, HMMA_SMEM_W>>>(
        chi, chi, ow, out, chi, chi, ow, out,
        ob, VV, HH, VV, 0, HH, 0, 0);
}

// round 8
// speedup vs baseline: 1.5079x; 1.5079x over previous
#include <cuda_runtime.h>
#include <cuda_fp16.h>
#include <math.h>
#include <stdint.h>

#define BB 64
#define LL 256
#define HH 1024
#define EE 1024
#define VV 50257
#define H3 3072

// ================= scratch (__device__ globals) =============================
__device__ __align__(16) __half g_xhi[BB * 1024];
__device__ __align__(16) __half g_xlo[BB * 1024];
__device__ __align__(16) __half g_hhi[BB * 1024];
__device__ __align__(16) __half g_hlo[BB * 1024];
__device__ __align__(16) __half g_chi[BB * 1024];
__device__ __align__(16) __half g_cat_hi[BB * 2 * HH];
__device__ __align__(16) __half g_cat_lo[BB * 2 * HH];
__device__ float g_gi[4 * BB * H3];            // k-split partials (GRU, 4-way)
__device__ float g_gh[4 * BB * H3];
__device__ float g_hb[BB];
__device__ float g_q[BB * HH];
__device__ float g_qpart[16 * BB * HH];
__device__ float g_scores[BB * LL];
__device__ float g_cpart[16 * BB * HH];

// ================= helpers ===================================================
__device__ __forceinline__ uint32_t smem_u32(const void* p) {
    uint32_t a;
    asm("{ .reg .u64 t; cvta.to.shared.u64 t, %1; cvt.u32.u64 %0, t; }"
        : "=r"(a) : "l"(p));
    return a;
}

__device__ __forceinline__ void ldsm_x4(uint32_t addr, uint32_t& d0, uint32_t& d1,
                                        uint32_t& d2, uint32_t& d3) {
    asm volatile("ldmatrix.sync.aligned.m8n8.x4.shared.b16 {%0,%1,%2,%3}, [%4];"
                 : "=r"(d0), "=r"(d1), "=r"(d2), "=r"(d3) : "r"(addr));
}

__device__ __forceinline__ void mma_f16(float* c, uint32_t a0, uint32_t a1,
                                        uint32_t a2, uint32_t a3,
                                        uint32_t b0, uint32_t b1) {
    asm volatile(
        "mma.sync.aligned.m16n8k16.row.col.f32.f16.f16.f32 "
        "{%0,%1,%2,%3}, {%4,%5,%6,%7}, {%8,%9}, {%0,%1,%2,%3};"
        : "+f"(c[0]), "+f"(c[1]), "+f"(c[2]), "+f"(c[3])
        : "r"(a0), "r"(a1), "r"(a2), "r"(a3), "r"(b0), "r"(b1));
}

__device__ __forceinline__ uint32_t pack_h(float a, float b) {
    __half2 t = __floats2half2_rn(a, b);
    return *reinterpret_cast<uint32_t*>(&t);
}

// ================= double-buffered fused-convert HMMA GEMM (fp16) ===========
// C[64, n] = sum_k fp32(A[64,k]) * W[n,k] (+bias), fp16 hi/lo compensated.
// NP=3: Ahi*Whi + Ahi*Wlo + Alo*Whi (err ~2^-22) — pre-softmax math.
// NP=2: Ahi*Whi + Ahi*Wlo           (err ~2^-12).
// NP=1: Ahi*Whi                     (err ~2^-11.5) — logits GEMM only.
// CTA 64x128, 8 warps 4x2 of 16x64. W fp32 read once, converted in-register.
// wtrans=0: W[n,k] stride K; wtrans=1: W[k,n] stride ldw.
// gridDim.z = split-K; partial z -> C + z*pstride (bias only if pstride==0).
#define STR 40

template <int NP>
__global__ __launch_bounds__(256, 2)
void hmma_gemm(const __half* __restrict__ Ahi0, const __half* __restrict__ Alo0,
               const float* __restrict__ W0, float* __restrict__ C0,
               const __half* __restrict__ Ahi1, const __half* __restrict__ Alo1,
               const float* __restrict__ W1, float* __restrict__ C1,
               const float* __restrict__ bias, int Ntot, int K, int ldc,
               long pstride, int lda, int ldw, int wtrans) {
    extern __shared__ __half sm[];

    constexpr bool HAS_ALO = (NP >= 3);
    constexpr bool HAS_WLO = (NP >= 2);
    constexpr int OFF_ALO_ = 64 * STR;
    constexpr int OFF_WHI_ = OFF_ALO_ + (HAS_ALO ? 64 * STR : 0);
    constexpr int OFF_WLO_ = OFF_WHI_ + 128 * STR;
    constexpr int STG_ELEMS = OFF_WLO_ + (HAS_WLO ? 128 * STR : 0);
    constexpr int STG_BYTES = STG_ELEMS * 2;

    const __half* Ahi = blockIdx.y ? Ahi1 : Ahi0;
    const __half* Alo = blockIdx.y ? Alo1 : Alo0;
    const float* W = blockIdx.y ? W1 : W0;
    float* C = (blockIdx.y ? C1 : C0) + (size_t)blockIdx.z * pstride;

    const int tid = threadIdx.x, wid = tid >> 5, lane = tid & 31;
    const int wr = wid & 3, wc = wid >> 2;
    const int n0 = blockIdx.x * 128;

    const int kper = K / gridDim.z;
    const int koff = blockIdx.z * kper;
    const int nchunks = kper >> 5;

    const int r = tid >> 1, hf = tid & 1;
    const bool wv = (n0 + r) < Ntot;
    const float* wrow = W + (size_t)(n0 + r) * K + koff + hf * 16;
    const float* wtb  = W + (size_t)(koff + hf * 16) * ldw + (n0 + r);
    const __half* arow_hi = Ahi + (size_t)(r & 63) * lda + koff + hf * 16;
    const __half* arow_lo = Alo + (size_t)(r & 63) * lda + koff + hf * 16;
    const bool do_a = (tid < 128);

    const int am = lane >> 3, aln = lane & 7;
    const int arow2 = wr * 16 + aln + (am & 1) * 8;
    const int akoff = (am >> 1) * 8;
    const uint32_t aHiB = smem_u32(&sm[arow2 * STR + akoff]);
    const uint32_t aLoB = smem_u32(&sm[OFF_ALO_ + arow2 * STR + akoff]);
    const int brow_base = wc * 64 + aln + (am >> 1) * 8;
    const int bkoff = (am & 1) * 8;
    const uint32_t bHiB = smem_u32(&sm[OFF_WHI_ + brow_base * STR + bkoff]);
    const uint32_t bLoB = smem_u32(&sm[OFF_WLO_ + brow_base * STR + bkoff]);

    float acc[8][4];
#pragma unroll
    for (int i = 0; i < 8; i++)
#pragma unroll
        for (int j = 0; j < 4; j++) acc[i][j] = 0.f;

    float wreg[16];
    uint4 ahreg[2], alreg[2];

    auto load_chunk = [&](int ck) {
        if (wv) {
            if (!wtrans) {
                const float4* p = (const float4*)(wrow + (size_t)ck * 32);
#pragma unroll
                for (int i = 0; i < 4; i++) {
                    float4 f = p[i];
                    wreg[i * 4 + 0] = f.x; wreg[i * 4 + 1] = f.y;
                    wreg[i * 4 + 2] = f.z; wreg[i * 4 + 3] = f.w;
                }
            } else {
                const float* p = wtb + (size_t)ck * 32 * ldw;
#pragma unroll
                for (int i = 0; i < 16; i++) wreg[i] = p[(size_t)i * ldw];
            }
        }
        if (do_a) {
            const uint4* ph = (const uint4*)(arow_hi + (size_t)ck * 32);
            ahreg[0] = ph[0]; ahreg[1] = ph[1];
            if (HAS_ALO) {
                const uint4* pl = (const uint4*)(arow_lo + (size_t)ck * 32);
                alreg[0] = pl[0]; alreg[1] = pl[1];
            }
        }
    };

    auto store_stage = [&](int st) {
        const int so = st * STG_ELEMS;
        int wb = so + OFF_WHI_ + r * STR + hf * 16;
        int wb2 = so + OFF_WLO_ + r * STR + hf * 16;
#pragma unroll
        for (int qq = 0; qq < 2; qq++) {
            uint4 hv;
            float f0 = wreg[qq * 8 + 0], f1 = wreg[qq * 8 + 1];
            float f2 = wreg[qq * 8 + 2], f3 = wreg[qq * 8 + 3];
            float f4 = wreg[qq * 8 + 4], f5 = wreg[qq * 8 + 5];
            float f6 = wreg[qq * 8 + 6], f7 = wreg[qq * 8 + 7];
            hv.x = pack_h(f0, f1); hv.y = pack_h(f2, f3);
            hv.z = pack_h(f4, f5); hv.w = pack_h(f6, f7);
            *(uint4*)&sm[wb + qq * 8] = hv;
            if (HAS_WLO) {
                uint4 lv;
                float h0 = __half2float(__float2half_rn(f0));
                float h1 = __half2float(__float2half_rn(f1));
                float h2 = __half2float(__float2half_rn(f2));
                float h3 = __half2float(__float2half_rn(f3));
                float h4 = __half2float(__float2half_rn(f4));
                float h5 = __half2float(__float2half_rn(f5));
                float h6 = __half2float(__float2half_rn(f6));
                float h7 = __half2float(__float2half_rn(f7));
                lv.x = pack_h(f0 - h0, f1 - h1);
                lv.y = pack_h(f2 - h2, f3 - h3);
                lv.z = pack_h(f4 - h4, f5 - h5);
                lv.w = pack_h(f6 - h6, f7 - h7);
                *(uint4*)&sm[wb2 + qq * 8] = lv;
            }
        }
        if (do_a) {
            int ab = so + r * STR + hf * 16;
            *(uint4*)&sm[ab + 0] = ahreg[0];
            *(uint4*)&sm[ab + 8] = ahreg[1];
            if (HAS_ALO) {
                int ab2 = so + OFF_ALO_ + r * STR + hf * 16;
                *(uint4*)&sm[ab2 + 0] = alreg[0];
                *(uint4*)&sm[ab2 + 8] = alreg[1];
            }
        }
    };

    if (!wv) {
#pragma unroll
        for (int i = 0; i < 16; i++) wreg[i] = 0.f;
    }

    load_chunk(0);
    store_stage(0);
    __syncthreads();

    for (int ck = 0; ck < nchunks; ck++) {
        const bool more = (ck + 1 < nchunks);
        if (more) load_chunk(ck + 1);

        const uint32_t so = (uint32_t)(ck & 1) * STG_BYTES;
#pragma unroll
        for (int ks = 0; ks < 2; ks++) {
            uint32_t ah0, ah1, ah2, ah3;
            uint32_t al0, al1, al2, al3;
            ldsm_x4(aHiB + so + ks * 32, ah0, ah1, ah2, ah3);
            if (HAS_ALO) ldsm_x4(aLoB + so + ks * 32, al0, al1, al2, al3);
#pragma unroll
            for (int nf = 0; nf < 4; nf++) {
                const uint32_t off = so + nf * (16 * STR * 2) + ks * 32;
                uint32_t bh0, bh1, bh2, bh3;
                ldsm_x4(bHiB + off, bh0, bh1, bh2, bh3);
                mma_f16(acc[nf * 2],     ah0, ah1, ah2, ah3, bh0, bh1);
                mma_f16(acc[nf * 2 + 1], ah0, ah1, ah2, ah3, bh2, bh3);
                if (HAS_WLO) {
                    uint32_t bl0, bl1, bl2, bl3;
                    ldsm_x4(bLoB + off, bl0, bl1, bl2, bl3);
                    mma_f16(acc[nf * 2],     ah0, ah1, ah2, ah3, bl0, bl1);
                    mma_f16(acc[nf * 2 + 1], ah0, ah1, ah2, ah3, bl2, bl3);
                }
                if (HAS_ALO) {
                    mma_f16(acc[nf * 2],     al0, al1, al2, al3, bh0, bh1);
                    mma_f16(acc[nf * 2 + 1], al0, al1, al2, al3, bh2, bh3);
                }
            }
        }

        if (more) store_stage((ck + 1) & 1);
        __syncthreads();
    }

    const int qrow = lane >> 2, qcol = (lane & 3) * 2;
    const int m0 = wr * 16 + qrow;
    const bool use_bias = (bias != nullptr) && (pstride == 0);
#pragma unroll
    for (int nf = 0; nf < 8; nf++) {
        int n = n0 + wc * 64 + nf * 8 + qcol;
        float b0v = 0.f, b1v = 0.f;
        if (use_bias) {
            if (n < Ntot) b0v = bias[n];
            if (n + 1 < Ntot) b1v = bias[n + 1];
        }
        if (n < Ntot) {
            C[(size_t)m0 * ldc + n] = acc[nf][0] + b0v;
            C[(size_t)(m0 + 8) * ldc + n] = acc[nf][2] + b0v;
        }
        if (n + 1 < Ntot) {
            C[(size_t)m0 * ldc + n + 1] = acc[nf][1] + b1v;
            C[(size_t)(m0 + 8) * ldc + n + 1] = acc[nf][3] + b1v;
        }
    }
}

#define SMEM_NP3 ((64 * STR + 64 * STR + 128 * STR + 128 * STR) * 2 * 2)
#define SMEM_NP1 ((64 * STR + 128 * STR) * 2 * 2)

// ================= fused hi/lo split prep (emb gather + h0) ==================
__global__ void split_all(const int* __restrict__ seq, const float* __restrict__ emb,
                          const float* __restrict__ h0,
                          __half* __restrict__ xhi, __half* __restrict__ xlo,
                          __half* __restrict__ hhi, __half* __restrict__ hlo) {
    int r = blockIdx.x, t = threadIdx.x;
    const float* src;
    __half *hi, *lo;
    int row;
    if (r < BB) {
        src = emb + (size_t)seq[r] * EE; hi = xhi; lo = xlo; row = r;
    } else {
        row = r - BB;
        src = h0 + (size_t)row * HH; hi = hhi; lo = hlo;
    }
    for (int j = t; j < 1024; j += 256) {
        float f = src[j];
        __half h = __float2half_rn(f);
        hi[row * 1024 + j] = h;
        lo[row * 1024 + j] = __float2half_rn(f - __half2float(h));
    }
}

// ================= split-K reducers ==========================================
__global__ void reduce_ba(const float* __restrict__ P, int nsplit, int ntot,
                          int N, const float* __restrict__ bias,
                          float* __restrict__ C, int act) {
    int idx = blockIdx.x * blockDim.x + threadIdx.x;
    if (idx >= ntot) return;
    float s = 0.f;
    for (int p = 0; p < nsplit; p++) s += P[(size_t)p * ntot + idx];
    if (bias) s += bias[idx % N];
    if (act) s = tanhf(s);
    C[idx] = s;
}

__global__ void reduce_tanh_split(const float* __restrict__ P,
                                  const float* __restrict__ bias,
                                  __half* __restrict__ hi) {
    int idx = blockIdx.x * blockDim.x + threadIdx.x;  // 65536
    float s = 0.f;
#pragma unroll
    for (int p = 0; p < 16; p++) s += P[(size_t)p * (BB * HH) + idx];
    s = tanhf(s + bias[idx & 1023]);
    hi[idx] = __float2half_rn(s);
}

// ================= fused GRU combine + hb reduction ==========================
__global__ void gru_combine_hb(const float* __restrict__ gi,
                               const float* __restrict__ gh,
                               const float* __restrict__ b_ih,
                               const float* __restrict__ b_hh,
                               const float* __restrict__ hprev,
                               const float* __restrict__ attn_b,
                               __half* __restrict__ cat_hi,
                               __half* __restrict__ cat_lo,
                               float* __restrict__ out_hidden,
                               float* __restrict__ hb) {
    int b = blockIdx.x, t = threadIdx.x;
    const int P = BB * H3;
    float hb_acc = 0.f;
#pragma unroll
    for (int ii = 0; ii < 4; ii++) {
        int j = t + ii * 256;
        size_t base = (size_t)b * H3 + j;
        float ir = 0.f, iz = 0.f, in_ = 0.f, hr = 0.f, hz = 0.f, hn = 0.f;
#pragma unroll
        for (int p = 0; p < 4; p++) {
            ir += gi[(size_t)p * P + base];
            iz += gi[(size_t)p * P + base + HH];
            in_ += gi[(size_t)p * P + base + 2 * HH];
            hr += gh[(size_t)p * P + base];
            hz += gh[(size_t)p * P + base + HH];
            hn += gh[(size_t)p * P + base + 2 * HH];
        }
        ir += b_ih[j]; iz += b_ih[HH + j]; in_ += b_ih[2 * HH + j];
        hr += b_hh[j]; hz += b_hh[HH + j]; hn += b_hh[2 * HH + j];
        float r = 1.f / (1.f + expf(-(ir + hr)));
        float z = 1.f / (1.f + expf(-(iz + hz)));
        float n = tanhf(in_ + r * hn);
        float hp = hprev[(size_t)b * HH + j];
        float hnew = (1.f - z) * n + z * hp;
        out_hidden[(size_t)b * HH + j] = hnew;
        __half h = __float2half_rn(hnew);
        cat_hi[(size_t)b * 2048 + j] = h;
        cat_lo[(size_t)b * 2048 + j] = __float2half_rn(hnew - __half2float(h));
        hb_acc += hnew * attn_b[j];
    }
    __shared__ float smr[256];
    smr[t] = hb_acc;
    __syncthreads();
    for (int st = 128; st > 0; st >>= 1) {
        if (t < st) smr[t] += smr[t + st];
        __syncthreads();
    }
    if (t == 0) hb[b] = smr[0];
}

// ================= attention kernels =========================================
__global__ void scores_kernel(const float* __restrict__ q,
                              const float* __restrict__ enc,
                              const float* __restrict__ hb,
                              float* __restrict__ scores) {
    int pair = blockIdx.x * 8 + (threadIdx.x >> 5);
    int lane = threadIdx.x & 31;
    int b = pair >> 8, l = pair & 255;
    const float* e = enc + ((size_t)l * BB + b) * HH;
    const float* qr = q + (size_t)b * HH;
    float s = 0.f;
#pragma unroll
    for (int i = 0; i < 8; i++) {
        int h = lane * 4 + i * 128;
        float4 ev = *(const float4*)(e + h);
        float4 qv = *(const float4*)(qr + h);
        s += ev.x * qv.x + ev.y * qv.y + ev.z * qv.z + ev.w * qv.w;
    }
#pragma unroll
    for (int o = 16; o > 0; o >>= 1) s += __shfl_xor_sync(0xffffffffu, s, o);
    if (lane == 0) scores[(size_t)b * LL + l] = s + hb[b];
}

// fused softmax (redundant per y-block) + context slice
__global__ void softmax_context(const float* __restrict__ scores,
                                const float* __restrict__ enc,
                                float* __restrict__ out_attn,
                                __half* __restrict__ cat_hi,
                                __half* __restrict__ cat_lo) {
    int b = blockIdx.x, t = threadIdx.x;
    __shared__ float w[256];
    __shared__ float red[128];
    float v0 = scores[(size_t)b * LL + t];
    float v1 = scores[(size_t)b * LL + t + 128];
    red[t] = fmaxf(v0, v1);
    __syncthreads();
    for (int s = 64; s > 0; s >>= 1) {
        if (t < s) red[t] = fmaxf(red[t], red[t + s]);
        __syncthreads();
    }
    float mx = red[0];
    __syncthreads();
    float e0 = expf(v0 - mx), e1 = expf(v1 - mx);
    red[t] = e0 + e1;
    __syncthreads();
    for (int s = 64; s > 0; s >>= 1) {
        if (t < s) red[t] += red[t + s];
        __syncthreads();
    }
    float inv = 1.f / red[0];
    float w0 = e0 * inv, w1 = e1 * inv;
    w[t] = w0; w[t + 128] = w1;
    if (blockIdx.y == 0) {
        out_attn[(size_t)b * LL + t] = w0;
        out_attn[(size_t)b * LL + t + 128] = w1;
    }
    __syncthreads();

    int hc = blockIdx.y * 128 + t;
    float acc = 0.f;
    const float* e = enc + (size_t)b * HH + hc;
    for (int l0 = 0; l0 < LL; l0 += 16) {
        float v[16];
#pragma unroll
        for (int u = 0; u < 16; u++)
            v[u] = e[(size_t)(l0 + u) * BB * HH];
#pragma unroll
        for (int u = 0; u < 16; u++)
            acc += w[l0 + u] * v[u];
    }
    size_t o = (size_t)b * 2048 + 1024 + hc;
    __half h = __float2half_rn(acc);
    cat_hi[o] = h;
    cat_lo[o] = __float2half_rn(acc - __half2float(h));
}

// ================= launch =====================================================
extern "C" void kernel_launch(void* const* d_in, const int* in_sizes, int n_in,
                              void* d_out, int out_size) {
    const int*   seq  = (const int*)d_in[0];
    const float* h0   = (const float*)d_in[1];
    const float* enc  = (const float*)d_in[2];
    const float* emb  = (const float*)d_in[3];
    const float* w_ih = (const float*)d_in[4];
    const float* w_hh = (const float*)d_in[5];
    const float* b_ih = (const float*)d_in[6];
    const float* b_hh = (const float*)d_in[7];
    const float* attw = (const float*)d_in[8];
    const float* attb = (const float*)d_in[9];
    const float* cw   = (const float*)d_in[10];
    const float* cb   = (const float*)d_in[11];
    const float* ow   = (const float*)d_in[12];
    const float* ob   = (const float*)d_in[13];

    float* out        = (float*)d_out;                  // [B, V]
    float* out_hidden = out + (size_t)BB * VV;          // [B, H]
    float* out_attn   = out_hidden + (size_t)BB * HH;   // [B, L]

    cudaFuncSetAttribute(hmma_gemm<3>, cudaFuncAttributeMaxDynamicSharedMemorySize,
                         SMEM_NP3);
    cudaFuncSetAttribute(hmma_gemm<1>, cudaFuncAttributeMaxDynamicSharedMemorySize,
                         SMEM_NP1);

    __half *xhi, *xlo, *hhi, *hlo, *chi, *cathi, *catlo;
    float *gi, *gh, *hb, *q, *qp, *sc, *cp;
    cudaGetSymbolAddress((void**)&xhi, g_xhi);
    cudaGetSymbolAddress((void**)&xlo, g_xlo);
    cudaGetSymbolAddress((void**)&hhi, g_hhi);
    cudaGetSymbolAddress((void**)&hlo, g_hlo);
    cudaGetSymbolAddress((void**)&chi, g_chi);
    cudaGetSymbolAddress((void**)&cathi, g_cat_hi);
    cudaGetSymbolAddress((void**)&catlo, g_cat_lo);
    cudaGetSymbolAddress((void**)&gi, g_gi);
    cudaGetSymbolAddress((void**)&gh, g_gh);
    cudaGetSymbolAddress((void**)&hb, g_hb);
    cudaGetSymbolAddress((void**)&q, g_q);
    cudaGetSymbolAddress((void**)&qp, g_qpart);
    cudaGetSymbolAddress((void**)&sc, g_scores);
    cudaGetSymbolAddress((void**)&cp, g_cpart);

    // 1) fp16 hi/lo splits: emb gather + h0
    split_all<<<128, 256>>>(seq, emb, h0, xhi, xlo, hhi, hlo);

    // 2) GRU gate GEMMs (3-pass; two problems via grid.y, split-K=4 -> 192 CTAs)
    hmma_gemm<3><<<dim3(24, 2, 4), 256, SMEM_NP3>>>(
        xhi, xlo, w_ih, gi, hhi, hlo, w_hh, gh,
        nullptr, H3, EE, H3, (long)BB * H3, EE, 0, 0);

    // 3) gates -> h_new (hidden output, cat hi/lo first half, hb)
    gru_combine_hb<<<BB, 256>>>(gi, gh, b_ih, b_hh, h0, attb,
                                cathi, catlo, out_hidden, hb);

    // 4) q = h_new @ attn_w (3-pass, transposed W, split-K=16 -> 128 CTAs)
    hmma_gemm<3><<<dim3(8, 1, 16), 256, SMEM_NP3>>>(
        cathi, catlo, attw, qp, cathi, catlo, attw, qp,
        nullptr, HH, HH, HH, (long)BB * HH, 2048, HH, 1);
    reduce_ba<<<(BB * HH) / 256, 256>>>(qp, 16, BB * HH, HH, nullptr, q, 0);

    // 5) scores = q . enc + hb ; fused softmax+context
    scores_kernel<<<2048, 256>>>(q, enc, hb, sc);
    softmax_context<<<dim3(BB, 8), 128>>>(sc, enc, out_attn, cathi, catlo);

    // 6) concat GEMM (3-pass, K=2048, split-K=16 -> 128 CTAs) -> tanh+fp16
    hmma_gemm<3><<<dim3(8, 1, 16), 256, SMEM_NP3>>>(
        cathi, catlo, cw, cp, cathi, catlo, cw, cp,
        nullptr, HH, 2048, HH, (long)BB * HH, 2048, 0, 0);
    reduce_tanh_split<<<(BB * HH) / 256, 256>>>(cp, cb, chi);

    // 7) big V-GEMM: single-pass fp16 (A hi x W hi) — half the MMA work of R6
    hmma_gemm<1><<<dim3((VV + 127) / 128, 1, 1), 256, SMEM_NP1>>>(
        chi, chi, ow, out, chi, chi, ow, out,
        ob, VV, HH, VV, 0, HH, 0, 0);
}